// round 7
// baseline (speedup 1.0000x reference)
#include <cuda_runtime.h>
#include <cstdint>

// ---------------------------------------------------------------------------
// HODLR linear: out = sum_i P_i( blockdiag(U_i V_i) x ) + blockdiag(D) x + b
//
// Tokens: 16384 (=4*4096), d_in = d_out = 4096, 6 low-rank levels rank 16,
// finest diag blocking 64x(64x64).
//
// Kernel 1 (proj): T[tok][layer][block][r] = sum_k x[tok][k]*us[layer][k][r]
//   exploiting that us_l flattened is [4096][16] row-major (block*chunk+local
//   == global k). 96 live accumulators per token, flushed at block ends.
// Kernel 2 (expand): out fine-block j gets, per layer l, coefficients of
//   paired block pb = (j >> (5-l)) ^ 1, expanded with vs_l[pb][:, lo..lo+63],
//   plus the dense diag block and bias.
// ---------------------------------------------------------------------------

#define NTHREADS 256

// Scratch: 16384 tokens x 2048 (2016 used, padded) coefficients.
__device__ __align__(16) float g_T[16384ull * 2048];

struct Ptr6 { const float* p[6]; };

// coefficient offsets per layer within a token's T row: cumsum of 32,64,...,1024
__host__ __device__ __forceinline__ int t_off(int l) {
    const int offs[6] = {0, 32, 96, 224, 480, 992};
    return offs[l];
}

// ===========================================================================
// Kernel 1: U projections, all 6 layers fused in one sweep over k.
// Grid: 256 CTAs (64 tokens each), 256 threads.
// Thread (tg = tid>>4, cg = tid&15): tokens tg*4..tg*4+3, rank cg, all layers.
// ===========================================================================
__global__ __launch_bounds__(NTHREADS) void hodlr_proj_kernel(
    const float* __restrict__ x, Ptr6 us)
{
    __shared__ float xs[64 * 68];    // 64 tokens x 64 k, row pad 68
    __shared__ float ws[6 * 1024];   // 6 layers x (64 k x 16 r), contiguous

    const int tid  = threadIdx.x;
    const int tg   = tid >> 4;       // token group 0..15
    const int cg   = tid & 15;       // rank 0..15
    const int tok0 = blockIdx.x * 64;

    float acc[4][6];
#pragma unroll
    for (int e = 0; e < 4; e++)
#pragma unroll
        for (int l = 0; l < 6; l++) acc[e][l] = 0.f;

    for (int kc = 0; kc < 64; kc++) {
        // ---- stage x tile (64 tok x 64 k) ----
        {
            const int row = tid >> 4, f4c = tid & 15;
#pragma unroll
            for (int p = 0; p < 4; p++) {
                const int r = row + p * 16;
                float4 v = *reinterpret_cast<const float4*>(
                    x + (size_t)(tok0 + r) * 4096 + kc * 64 + f4c * 4);
                *reinterpret_cast<float4*>(xs + r * 68 + f4c * 4) = v;
            }
        }
        // ---- stage weight slices: us_l flat [4096][16], rows kc*64..kc*64+63 ----
#pragma unroll
        for (int p = 0; p < 6; p++) {
            const int idx = p * 256 + tid;       // float4 index, 1536 total
            const int l = idx >> 8, f4i = idx & 255;
            float4 v = *reinterpret_cast<const float4*>(
                us.p[l] + (size_t)kc * 1024 + f4i * 4);
            *reinterpret_cast<float4*>(ws + l * 1024 + f4i * 4) = v;
        }
        __syncthreads();

        // ---- accumulate ----
#pragma unroll 2
        for (int kk = 0; kk < 64; kk += 4) {
            float xr[4][4];
#pragma unroll
            for (int e = 0; e < 4; e++) {
                float4 v = *reinterpret_cast<const float4*>(
                    xs + (tg * 4 + e) * 68 + kk);
                xr[e][0] = v.x; xr[e][1] = v.y; xr[e][2] = v.z; xr[e][3] = v.w;
            }
#pragma unroll
            for (int q = 0; q < 4; q++) {
                float w[6];
#pragma unroll
                for (int l = 0; l < 6; l++)
                    w[l] = ws[l * 1024 + (kk + q) * 16 + cg];
#pragma unroll
                for (int e = 0; e < 4; e++)
#pragma unroll
                    for (int l = 0; l < 6; l++)
                        acc[e][l] += xr[e][q] * w[l];
            }
        }
        __syncthreads();   // before next chunk overwrites smem

        // ---- flush layers whose block ends at this chunk ----
#pragma unroll
        for (int l = 0; l < 6; l++) {
            const int mask = (1 << (5 - l)) - 1;
            if (((kc + 1) & mask) == 0) {
                const int b = kc >> (5 - l);
#pragma unroll
                for (int e = 0; e < 4; e++) {
                    g_T[(size_t)(tok0 + tg * 4 + e) * 2048 + t_off(l) + b * 16 + cg]
                        = acc[e][l];
                    acc[e][l] = 0.f;
                }
            }
        }
    }
}

// ===========================================================================
// Kernel 2: V expansion + diag + bias for one 64-wide output block.
// Grid: (64 blocks j, 256 token tiles), 256 threads.
// Thread (tg, colg): 4 tokens x 4 cols register tile.
// Dynamic smem: xs 4352 | dss 4096 | Ts 6400 | vss 6144 floats = 83968 B.
// ===========================================================================
__global__ __launch_bounds__(NTHREADS) void hodlr_expand_kernel(
    const float* __restrict__ x, Ptr6 vs, const float* __restrict__ ds,
    const float* __restrict__ bias, float* __restrict__ out)
{
    extern __shared__ float sm[];
    float* xs  = sm;            // [64][68]
    float* dss = sm + 4352;     // [64 k][64 col]
    float* Ts  = sm + 8448;     // [64 tok][100] (96 used)
    float* vss = sm + 14848;    // [96 c][64 col]

    const int tid  = threadIdx.x;
    const int j    = blockIdx.x;        // output fine block 0..63
    const int tok0 = blockIdx.y * 64;
    const int tg   = tid >> 4;
    const int colg = tid & 15;

    int pb[6], lo[6];
#pragma unroll
    for (int l = 0; l < 6; l++) {
        const int shift = 5 - l;
        pb[l] = (j >> shift) ^ 1;
        lo[l] = (j & ((1 << shift) - 1)) * 64;
    }

    // ---- stage x block j (64 tok x 64) ----
    {
        const int row = tid >> 4, f4c = tid & 15;
#pragma unroll
        for (int p = 0; p < 4; p++) {
            const int r = row + p * 16;
            float4 v = *reinterpret_cast<const float4*>(
                x + (size_t)(tok0 + r) * 4096 + j * 64 + f4c * 4);
            *reinterpret_cast<float4*>(xs + r * 68 + f4c * 4) = v;
        }
    }
    // ---- stage ds[j] (64x64) ----
#pragma unroll
    for (int p = 0; p < 4; p++) {
        const int f4i = p * 256 + tid;
        float4 v = *reinterpret_cast<const float4*>(ds + (size_t)j * 4096 + f4i * 4);
        *reinterpret_cast<float4*>(dss + f4i * 4) = v;
    }
    // ---- stage vs slices: vss[l*16+r][col] = vs_l[pb][r][lo+col] ----
#pragma unroll
    for (int p = 0; p < 6; p++) {
        const int idx = p * 256 + tid;      // 1536 float4
        const int row = idx >> 4, f4 = idx & 15;
        const int l = row >> 4, r = row & 15;
        const int cl = 1 << (11 - l);
        float4 v = *reinterpret_cast<const float4*>(
            vs.p[l] + (size_t)(pb[l] * 16 + r) * cl + lo[l] + f4 * 4);
        *reinterpret_cast<float4*>(vss + row * 64 + f4 * 4) = v;
    }
    // ---- stage T slices: Ts[tok][l*16+r] = g_T[tok][off_l + pb*16 + r] ----
#pragma unroll
    for (int p = 0; p < 6; p++) {
        const int idx = p * 256 + tid;      // 1536 float4 (64 tok x 24 f4)
        const int tok = idx / 24, c4 = idx % 24;
        const int c = c4 * 4, l = c >> 4, r = c & 15;
        float4 v = *reinterpret_cast<const float4*>(
            &g_T[(size_t)(tok0 + tok) * 2048 + t_off(l) + pb[l] * 16 + r]);
        *reinterpret_cast<float4*>(Ts + tok * 100 + c) = v;
    }
    __syncthreads();

    float acc[4][4];
#pragma unroll
    for (int e = 0; e < 4; e++)
#pragma unroll
        for (int c = 0; c < 4; c++) acc[e][c] = 0.f;

    // ---- diag: acc += x[:,k] * ds[k,:] ----
#pragma unroll 4
    for (int kk = 0; kk < 64; kk += 4) {
        float xr[4][4], dr[4][4];
#pragma unroll
        for (int e = 0; e < 4; e++) {
            float4 v = *reinterpret_cast<const float4*>(xs + (tg * 4 + e) * 68 + kk);
            xr[e][0] = v.x; xr[e][1] = v.y; xr[e][2] = v.z; xr[e][3] = v.w;
        }
#pragma unroll
        for (int q = 0; q < 4; q++) {
            float4 v = *reinterpret_cast<const float4*>(dss + (kk + q) * 64 + colg * 4);
            dr[q][0] = v.x; dr[q][1] = v.y; dr[q][2] = v.z; dr[q][3] = v.w;
        }
#pragma unroll
        for (int e = 0; e < 4; e++)
#pragma unroll
            for (int q = 0; q < 4; q++)
#pragma unroll
                for (int c = 0; c < 4; c++)
                    acc[e][c] += xr[e][q] * dr[q][c];
    }

    // ---- low rank: acc += T[:,c] * vss[c,:] over 96 coefficients ----
#pragma unroll 4
    for (int cc = 0; cc < 96; cc += 4) {
        float tr[4][4], vr[4][4];
#pragma unroll
        for (int e = 0; e < 4; e++) {
            float4 v = *reinterpret_cast<const float4*>(Ts + (tg * 4 + e) * 100 + cc);
            tr[e][0] = v.x; tr[e][1] = v.y; tr[e][2] = v.z; tr[e][3] = v.w;
        }
#pragma unroll
        for (int q = 0; q < 4; q++) {
            float4 v = *reinterpret_cast<const float4*>(vss + (cc + q) * 64 + colg * 4);
            vr[q][0] = v.x; vr[q][1] = v.y; vr[q][2] = v.z; vr[q][3] = v.w;
        }
#pragma unroll
        for (int e = 0; e < 4; e++)
#pragma unroll
            for (int q = 0; q < 4; q++)
#pragma unroll
                for (int c = 0; c < 4; c++)
                    acc[e][c] += tr[e][q] * vr[q][c];
    }

    // ---- bias + store ----
    float4 bv = *reinterpret_cast<const float4*>(bias + j * 64 + colg * 4);
#pragma unroll
    for (int e = 0; e < 4; e++) {
        float4 o;
        o.x = acc[e][0] + bv.x;
        o.y = acc[e][1] + bv.y;
        o.z = acc[e][2] + bv.z;
        o.w = acc[e][3] + bv.w;
        *reinterpret_cast<float4*>(
            out + (size_t)(tok0 + tg * 4 + e) * 4096 + j * 64 + colg * 4) = o;
    }
}

// ===========================================================================
// Launch
// ===========================================================================
extern "C" void kernel_launch(void* const* d_in, const int* in_sizes, int n_in,
                              void* d_out, int out_size)
{
    (void)in_sizes; (void)n_in; (void)out_size;

    // metadata order: x, us0, vs0, us1, vs1, ..., us5, vs5, ds, bias
    const float* x    = (const float*)d_in[0];
    Ptr6 us, vs;
    for (int l = 0; l < 6; l++) {
        us.p[l] = (const float*)d_in[1 + 2 * l];
        vs.p[l] = (const float*)d_in[2 + 2 * l];
    }
    const float* ds   = (const float*)d_in[13];
    const float* bias = (const float*)d_in[14];
    float* out        = (float*)d_out;

    const int SMEM2 = 20992 * (int)sizeof(float);  // 83968 B
    cudaFuncSetAttribute(hodlr_expand_kernel,
                         cudaFuncAttributeMaxDynamicSharedMemorySize, SMEM2);

    hodlr_proj_kernel<<<256, NTHREADS>>>(x, us);
    hodlr_expand_kernel<<<dim3(64, 256), NTHREADS, SMEM2>>>(x, vs, ds, bias, out);
}